// round 12
// baseline (speedup 1.0000x reference)
#include <cuda_runtime.h>
#include <cuda_bf16.h>
#include <cstdint>
#include <math.h>

#define EPSV 0.001f
#define MM (1024*1024)

// ---------------- device scratch ----------------
__device__ __align__(16) __nv_bfloat16 g_Thi[3u*1024u*3072u];  // [col][k]
__device__ __align__(16) __nv_bfloat16 g_Tlo[3u*1024u*3072u];
__device__ float g_Pp[24u*MM];  // split-K partials: [mat*8+ks], mat 0:X1 1:X3 2:X2
__device__ float g_E[MM];
__device__ float g_H22[MM];
__device__ float g_t1[3072];
__device__ float g_s[3072];
__device__ float g_pre[1024];
__device__ float g_eps[1024];
__device__ float g_b[1024];
__device__ float g_xA[1024];
__device__ float g_xB[1024];

// ---------------- helpers ----------------
__device__ __forceinline__ float warpSum(float v) {
#pragma unroll
    for (int o = 16; o; o >>= 1) v += __shfl_down_sync(0xffffffffu, v, o);
    return v;
}
__device__ __forceinline__ float blockSum(float v) {
    __shared__ float sh[32];
    int lane = threadIdx.x & 31, wid = threadIdx.x >> 5;
    v = warpSum(v);
    if (lane == 0) sh[wid] = v;
    __syncthreads();
    if (wid == 0) {
        v = (lane < (int)(blockDim.x >> 5)) ? sh[lane] : 0.f;
        v = warpSum(v);
    }
    return v;
}
__device__ __forceinline__ float2 bf2f(uint32_t u) {
    __nv_bfloat162 h = *(__nv_bfloat162*)&u;
    return __bfloat1622float2(h);
}
__device__ __forceinline__ uint32_t smem_u32(const void* p) {
    uint32_t a;
    asm("{ .reg .u64 t; cvta.to.shared.u64 t, %1; cvt.u32.u64 %0, t; }" : "=r"(a) : "l"(p));
    return a;
}
#define CPA16(d, s) asm volatile("cp.async.ca.shared.global [%0], [%1], 16;" :: "r"(d), "l"(s))
#define CP_COMMIT() asm volatile("cp.async.commit_group;")
#define CP_WAIT0()  asm volatile("cp.async.wait_group 0;")
#define CP_WAIT1()  asm volatile("cp.async.wait_group 1;")
#define LDSM4(r0, r1, r2, r3, a) \
    asm volatile("ldmatrix.sync.aligned.m8n8.x4.shared.b16 {%0,%1,%2,%3}, [%4];" \
        : "=r"(r0), "=r"(r1), "=r"(r2), "=r"(r3) : "r"(a))
#define MMA_BF16(d, a, b) \
    asm volatile("mma.sync.aligned.m16n8k16.row.col.f32.bf16.bf16.f32 " \
        "{%0,%1,%2,%3},{%4,%5,%6,%7},{%8,%9},{%0,%1,%2,%3};" \
        : "+f"((d)[0]), "+f"((d)[1]), "+f"((d)[2]), "+f"((d)[3]) \
        : "r"((a)[0]), "r"((a)[1]), "r"((a)[2]), "r"((a)[3]), "r"((b)[0]), "r"((b)[1]))

// smem tile: 128 rows x 32 bf16 (64B/row), chunk swizzle c ^= (row>>1)&3
__device__ __forceinline__ uint32_t tileOff(int row, int c) {
    return (uint32_t)(row * 64 + ((c ^ ((row >> 1) & 3)) << 4));
}

// ---------------- t1 = X1 @ xi ----------------
__global__ void k_t1(const float* __restrict__ X, const float* __restrict__ xi) {
    int w = threadIdx.x >> 5, lane = threadIdx.x & 31;
    int r = blockIdx.x * 8 + w;
    const float4* row = (const float4*)(X + (size_t)r * 3072);
    const float4* xv4 = (const float4*)xi;
    float s = 0.f;
#pragma unroll
    for (int it = 0; it < 8; ++it) {
        float4 a = row[lane + it * 32];
        float4 b = xv4[lane + it * 32];
        s += a.x * b.x + a.y * b.y + a.z * b.z + a.w * b.w;
    }
    s = warpSum(s);
    if (lane == 0) g_t1[r] = s;
}

// ---------------- split & transpose: X -> bf16 hi/lo, [col][k], 64x64 tiles ----------------
__global__ __launch_bounds__(256) void k_split(const float* __restrict__ X) {
    __shared__ float tile[64][65];
    int bx = blockIdx.x % 48, by = blockIdx.x / 48;
    int c0 = bx * 64, r0 = by * 64;
    int tid = threadIdx.x;
#pragma unroll
    for (int it = 0; it < 16; ++it) {
        int elem = it * 256 + tid;
        int row = elem >> 6, col = elem & 63;
        tile[row][col] = X[(size_t)(r0 + row) * 3072 + c0 + col];
    }
    __syncthreads();
#pragma unroll
    for (int it = 0; it < 8; ++it) {
        int elem = it * 256 + tid;
        int col = elem >> 5, rp = elem & 31;
        float v0 = tile[2 * rp][col];
        float v1 = tile[2 * rp + 1][col];
        __nv_bfloat16 h0 = __float2bfloat16(v0);
        __nv_bfloat16 h1 = __float2bfloat16(v1);
        __nv_bfloat162 hi2; hi2.x = h0; hi2.y = h1;
        __nv_bfloat162 lo2;
        lo2.x = __float2bfloat16(v0 - __bfloat162float(h0));
        lo2.y = __float2bfloat16(v1 - __bfloat162float(h1));
        size_t o = ((size_t)(c0 + col) * 3072u + r0 + 2 * rp) >> 1;
        ((__nv_bfloat162*)g_Thi)[o] = hi2;
        ((__nv_bfloat162*)g_Tlo)[o] = lo2;
    }
}

// ---------------- pre = -X2^T t1 + D12 @ w ----------------
__global__ void k_pre2(const float* __restrict__ D12, const float* __restrict__ w) {
    int wid = threadIdx.x >> 5, lane = threadIdx.x & 31;
    int i = blockIdx.x * 8 + wid;
    const uint4* hi = (const uint4*)(g_Thi + (size_t)(1024 + i) * 3072);
    const uint4* lo = (const uint4*)(g_Tlo + (size_t)(1024 + i) * 3072);
    const float4* t1 = (const float4*)g_t1;
    float s = 0.f;
#pragma unroll
    for (int it = 0; it < 12; ++it) {
        int u = lane + it * 32;
        uint4 hv = hi[u];
        uint4 lv = lo[u];
        float4 ta = t1[2 * u], tb = t1[2 * u + 1];
        float2 h0 = bf2f(hv.x), l0 = bf2f(lv.x);
        float2 h1 = bf2f(hv.y), l1 = bf2f(lv.y);
        float2 h2 = bf2f(hv.z), l2 = bf2f(lv.z);
        float2 h3 = bf2f(hv.w), l3 = bf2f(lv.w);
        s += (h0.x + l0.x) * ta.x + (h0.y + l0.y) * ta.y + (h1.x + l1.x) * ta.z + (h1.y + l1.y) * ta.w;
        s += (h2.x + l2.x) * tb.x + (h2.y + l2.y) * tb.y + (h3.x + l3.x) * tb.z + (h3.y + l3.y) * tb.w;
    }
    const float4* dd = (const float4*)(D12 + (size_t)i * 512);
    const float4* wv = (const float4*)w;
    float s2 = 0.f;
#pragma unroll
    for (int it = 0; it < 4; ++it) {
        float4 a = dd[lane + it * 32];
        float4 b = wv[lane + it * 32];
        s2 += a.x * b.x + a.y * b.y + a.z * b.z + a.w * b.w;
    }
    float v = warpSum(s2 - s);
    if (lane == 0) g_pre[i] = v;
}

// ---------------- Gram GEMM via mma.sync, split-K 8 (864 CTAs), occ 2 ----------------
#define GRAM_SMEM 66560
__global__ __launch_bounds__(256, 2) void k_gram() {
    extern __shared__ char smem[];
    uint32_t sb = smem_u32(smem);
    int tid = threadIdx.x;
    int lane = tid & 31, warp = tid >> 5;
    int warpM = warp & 1, warpN = warp >> 1;

    int job = blockIdx.x;          // 0..863
    int ks = job & 7;              // K chunk: ks*384
    int t = job >> 3;              // 0..107
    int mat = t / 36;
    int rem = t % 36, ti = 0, span = 8;
    while (rem >= span) { rem -= span; span--; ti++; }
    int tj = ti + rem;
    const int blkmap[3] = {0, 2, 1};
    size_t blkOff = (size_t)blkmap[mat] * (1024u * 3072u);
    float* outP = g_Pp + (size_t)(mat * 8 + ks) * MM;
    int i0 = ti * 128, j0 = tj * 128;
    int kOff = ks * 384;

    const __nv_bfloat16* srcs[4];
    srcs[0] = g_Thi + blkOff + (size_t)i0 * 3072 + kOff;
    srcs[1] = g_Tlo + blkOff + (size_t)i0 * 3072 + kOff;
    srcs[2] = g_Thi + blkOff + (size_t)j0 * 3072 + kOff;
    srcs[3] = g_Tlo + blkOff + (size_t)j0 * 3072 + kOff;

    float acc[4][4][4];
#pragma unroll
    for (int a = 0; a < 4; ++a)
#pragma unroll
        for (int b = 0; b < 4; ++b)
#pragma unroll
            for (int c = 0; c < 4; ++c) acc[a][b][c] = 0.f;

    int lrow = tid & 127;
    int lc0 = tid >> 7;
    const int NST = 12;  // 384 / 32

    {
        uint32_t sbase = sb;
#pragma unroll
        for (int pc = 0; pc < 4; ++pc) {
            const __nv_bfloat16* src = srcs[pc] + (size_t)lrow * 3072;
#pragma unroll
            for (int it = 0; it < 2; ++it) {
                int c = lc0 + it * 2;
                CPA16(sbase + pc * 8192u + tileOff(lrow, c), src + c * 8);
            }
        }
        CP_COMMIT();
    }

    for (int kt = 0; kt < NST; ++kt) {
        int s = kt & 1;
        if (kt + 1 < NST) {
            uint32_t sbase = sb + (uint32_t)((kt + 1) & 1) * 32768u;
            int kIdx = (kt + 1) * 32;
#pragma unroll
            for (int pc = 0; pc < 4; ++pc) {
                const __nv_bfloat16* src = srcs[pc] + (size_t)lrow * 3072 + kIdx;
#pragma unroll
                for (int it = 0; it < 2; ++it) {
                    int c = lc0 + it * 2;
                    CPA16(sbase + pc * 8192u + tileOff(lrow, c), src + c * 8);
                }
            }
            CP_COMMIT();
            CP_WAIT1();
        } else {
            CP_WAIT0();
        }
        __syncthreads();

        uint32_t SA_hi = sb + (uint32_t)s * 32768u;
        uint32_t SA_lo = SA_hi + 8192u;
        uint32_t SB_hi = SA_hi + 16384u;
        uint32_t SB_lo = SA_hi + 24576u;

#pragma unroll
        for (int kb = 0; kb < 2; ++kb) {
            uint32_t ah[4][4], al[4][4], bh[4][2], bl[4][2];
            int rA = warpM * 64 + (lane & 15);
            int cA = kb * 2 + (lane >> 4);
#pragma unroll
            for (int mi = 0; mi < 4; ++mi) {
                uint32_t off = tileOff(rA + mi * 16, cA);
                LDSM4(ah[mi][0], ah[mi][1], ah[mi][2], ah[mi][3], SA_hi + off);
                LDSM4(al[mi][0], al[mi][1], al[mi][2], al[mi][3], SA_lo + off);
            }
            int grp = lane >> 3;
            int cB = kb * 2 + (grp & 1);
#pragma unroll
            for (int p = 0; p < 2; ++p) {
                int row = warpN * 32 + (p * 2 + (grp >> 1)) * 8 + (lane & 7);
                uint32_t off = tileOff(row, cB);
                uint32_t r0, r1, r2, r3;
                LDSM4(r0, r1, r2, r3, SB_hi + off);
                bh[p * 2][0] = r0; bh[p * 2][1] = r1;
                bh[p * 2 + 1][0] = r2; bh[p * 2 + 1][1] = r3;
                LDSM4(r0, r1, r2, r3, SB_lo + off);
                bl[p * 2][0] = r0; bl[p * 2][1] = r1;
                bl[p * 2 + 1][0] = r2; bl[p * 2 + 1][1] = r3;
            }
            // 3 product passes: same-acc reuse distance = 16 issues (hides HMMA latency)
#pragma unroll
            for (int mi = 0; mi < 4; ++mi)
#pragma unroll
                for (int ni = 0; ni < 4; ++ni)
                    MMA_BF16(acc[mi][ni], ah[mi], bh[ni]);
#pragma unroll
            for (int mi = 0; mi < 4; ++mi)
#pragma unroll
                for (int ni = 0; ni < 4; ++ni)
                    MMA_BF16(acc[mi][ni], ah[mi], bl[ni]);
#pragma unroll
            for (int mi = 0; mi < 4; ++mi)
#pragma unroll
                for (int ni = 0; ni < 4; ++ni)
                    MMA_BF16(acc[mi][ni], al[mi], bh[ni]);
        }
        __syncthreads();
    }

    // epilogue: stage through smem (129 pitch), write both mirrored halves coalesced
    float (*Ts)[129] = (float(*)[129])smem;
    int g = lane >> 2, tg = lane & 3;
#pragma unroll
    for (int mi = 0; mi < 4; ++mi) {
        int r0 = warpM * 64 + mi * 16 + g;
#pragma unroll
        for (int ni = 0; ni < 4; ++ni) {
            int col = warpN * 32 + ni * 8 + tg * 2;
            Ts[r0][col] = acc[mi][ni][0];
            Ts[r0][col + 1] = acc[mi][ni][1];
            Ts[r0 + 8][col] = acc[mi][ni][2];
            Ts[r0 + 8][col + 1] = acc[mi][ni][3];
        }
    }
    __syncthreads();
    {
        int row = tid >> 1, ch = (tid & 1) * 64;
        float* o = outP + (size_t)(i0 + row) * 1024 + j0 + ch;
#pragma unroll
        for (int q = 0; q < 16; ++q) {
            float4 v = make_float4(Ts[row][ch + 4 * q], Ts[row][ch + 4 * q + 1],
                                   Ts[row][ch + 4 * q + 2], Ts[row][ch + 4 * q + 3]);
            ((float4*)o)[q] = v;
        }
        if (ti != tj) {
            float* o2 = outP + (size_t)(j0 + row) * 1024 + i0 + ch;
#pragma unroll
            for (int q = 0; q < 16; ++q) {
                float4 v = make_float4(Ts[ch + 4 * q][row], Ts[ch + 4 * q + 1][row],
                                       Ts[ch + 4 * q + 2][row], Ts[ch + 4 * q + 3][row]);
                ((float4*)o2)[q] = v;
            }
        }
    }
}

// ---------------- combineH: H22 = sum of 8 partials ----------------
__global__ void k_combineH() {
    int i = blockIdx.x * 256 + threadIdx.x;  // grid 1024, float4
    float4 r = make_float4(0.f, 0.f, 0.f, 0.f);
#pragma unroll
    for (int p = 16; p < 24; ++p) {
        float4 a = ((const float4*)(g_Pp + (size_t)p * MM))[i];
        r.x += a.x; r.y += a.y; r.z += a.z; r.w += a.w;
    }
    ((float4*)g_H22)[i] = r;
}

// ---------------- combineE: E = 0.5(ΣPE + Y - Y^T) + epsI ----------------
__global__ void k_combineE(const float* __restrict__ Y) {
    __shared__ float Yt[32][33];
    int bj = blockIdx.x & 31, bi = blockIdx.x >> 5;
    int tx = threadIdx.x & 31, ty = threadIdx.x >> 5;
#pragma unroll
    for (int it = 0; it < 4; ++it) {
        int jr = bj * 32 + ty + it * 8;
        Yt[ty + it * 8][tx] = Y[(size_t)jr * 1024 + bi * 32 + tx];
    }
    __syncthreads();
#pragma unroll
    for (int it = 0; it < 4; ++it) {
        int i = bi * 32 + ty + it * 8;
        int j = bj * 32 + tx;
        size_t idx = (size_t)i * 1024 + j;
        float s = 0.f;
#pragma unroll
        for (int p = 0; p < 16; ++p) s += g_Pp[(size_t)p * MM + idx];
        float e = 0.5f * (s + Y[idx] - Yt[tx][ty + it * 8]);
        if (i == j) e += EPSV;
        g_E[idx] = e;
    }
}

// ---------------- blocked tanh forward substitution (chunk=32) ----------------
__global__ __launch_bounds__(1024) void k_scan() {
    int j = threadIdx.x, wid = j >> 5, lane = j & 31;
    __shared__ float s_eps[1024];
    float accJ = 0.f;
    float pre_j = g_pre[j];
    float li = 1.0f / (g_H22[(size_t)j * 1024 + j] + EPSV);
    for (int c = 0; c < 32; ++c) {
        int base = c * 32;
        if (wid == c) {
            float colreg[32];
#pragma unroll
            for (int k = 0; k < 32; ++k)
                colreg[k] = g_H22[(size_t)(base + k) * 1024 + base + lane];
            float within = 0.f, myeps = 0.f;
            float v_base = pre_j + accJ;
#pragma unroll
            for (int k = 0; k < 32; ++k) {
                if (lane == k) myeps = tanhf((v_base + within) * li);
                float e = __shfl_sync(0xffffffffu, myeps, k);
                if (lane > k) within = fmaf(-colreg[k], e, within);
            }
            s_eps[base + lane] = myeps;
        }
        __syncthreads();
        if (j >= base + 32) {
#pragma unroll
            for (int k = 0; k < 32; ++k)
                accJ = fmaf(-g_H22[(size_t)(base + k) * 1024 + j], s_eps[base + k], accJ);
        }
    }
    g_eps[j] = s_eps[j];
}

// ---------------- s = t1 + X2 @ eps ----------------
__global__ void k_s(const float* __restrict__ X) {
    int w = threadIdx.x >> 5, lane = threadIdx.x & 31;
    int r = blockIdx.x * 8 + w;
    const float4* row = (const float4*)(X + (size_t)r * 3072 + 1024);
    const float4* ev4 = (const float4*)g_eps;
    float s = 0.f;
#pragma unroll
    for (int it = 0; it < 8; ++it) {
        float4 a = row[lane + it * 32];
        float4 b = ev4[lane + it * 32];
        s += a.x * b.x + a.y * b.y + a.z * b.z + a.w * b.w;
    }
    s = warpSum(s);
    if (lane == 0) g_s[r] = g_t1[r] + s;
}

// ---------------- b = X3^T s + B2 @ w ----------------
__global__ void k_b2(const float* __restrict__ B2, const float* __restrict__ w) {
    int wid = threadIdx.x >> 5, lane = threadIdx.x & 31;
    int i = blockIdx.x * 8 + wid;
    const uint4* hi = (const uint4*)(g_Thi + (size_t)(2048 + i) * 3072);
    const uint4* lo = (const uint4*)(g_Tlo + (size_t)(2048 + i) * 3072);
    const float4* sv = (const float4*)g_s;
    float s = 0.f;
#pragma unroll
    for (int it = 0; it < 12; ++it) {
        int u = lane + it * 32;
        uint4 hv = hi[u];
        uint4 lv = lo[u];
        float4 ta = sv[2 * u], tb = sv[2 * u + 1];
        float2 h0 = bf2f(hv.x), l0 = bf2f(lv.x);
        float2 h1 = bf2f(hv.y), l1 = bf2f(lv.y);
        float2 h2 = bf2f(hv.z), l2 = bf2f(lv.z);
        float2 h3 = bf2f(hv.w), l3 = bf2f(lv.w);
        s += (h0.x + l0.x) * ta.x + (h0.y + l0.y) * ta.y + (h1.x + l1.x) * ta.z + (h1.y + l1.y) * ta.w;
        s += (h2.x + l2.x) * tb.x + (h2.y + l2.y) * tb.y + (h3.x + l3.x) * tb.z + (h3.y + l3.y) * tb.w;
    }
    const float4* bb = (const float4*)(B2 + (size_t)i * 512);
    const float4* wv = (const float4*)w;
    float s2 = 0.f;
#pragma unroll
    for (int it = 0; it < 4; ++it) {
        float4 a = bb[lane + it * 32];
        float4 b = wv[lane + it * 32];
        s2 += a.x * b.x + a.y * b.y + a.z * b.z + a.w * b.w;
    }
    float v = warpSum(s + s2);
    if (lane == 0) { g_b[i] = v; g_xA[i] = 0.f; }
}

// ---------------- Richardson step ----------------
__global__ void k_rich(float alpha, int flip) {
    const float* xs = flip ? g_xB : g_xA;
    float* xd = flip ? g_xA : g_xB;
    int i = blockIdx.x;
    int t = threadIdx.x;
    const float4* Er = (const float4*)(g_E + (size_t)i * 1024);
    const float4* xv = (const float4*)xs;
    float4 e = Er[t];
    float4 x = xv[t];
    float s = e.x * x.x + e.y * x.y + e.z * x.z + e.w * x.w;
    s = blockSum(s);
    if (t == 0) xd[i] = xs[i] + alpha * (g_b[i] - s);
}

// ---------------- output assembly ----------------
__global__ void k_final(const float* __restrict__ C2, const float* __restrict__ D21,
                        const float* __restrict__ D22, const float* __restrict__ xi,
                        const float* __restrict__ w, float* __restrict__ out) {
    int i = blockIdx.x;
    if (i >= 512) {
        if (threadIdx.x == 0) out[i] = g_xA[i - 512];
        return;
    }
    int t = threadIdx.x;
    float s = 0.f;
    for (int k = t; k < 1024; k += 256)
        s += C2[i * 1024 + k] * xi[k] + D21[i * 1024 + k] * g_eps[k];
    for (int k = t; k < 512; k += 256) s += D22[i * 512 + k] * w[k];
    float v = blockSum(s);
    if (t == 0) out[i] = v;
}

// ---------------- host ----------------
extern "C" void kernel_launch(void* const* d_in, const int* in_sizes, int n_in,
                              void* d_out, int out_size) {
    const float* w   = (const float*)d_in[1];
    const float* xi  = (const float*)d_in[2];
    const float* X   = (const float*)d_in[3];
    const float* Y   = (const float*)d_in[4];
    const float* B2  = (const float*)d_in[5];
    const float* C2  = (const float*)d_in[6];
    const float* D21 = (const float*)d_in[7];
    const float* D22 = (const float*)d_in[8];
    const float* D12 = (const float*)d_in[9];
    float* out = (float*)d_out;

    cudaFuncSetAttribute(k_gram, cudaFuncAttributeMaxDynamicSharedMemorySize, GRAM_SMEM);

    k_t1<<<384, 256>>>(X, xi);           // 1
    k_split<<<2304, 256>>>(X);           // 2
    k_pre2<<<128, 256>>>(D12, w);        // 3
    k_gram<<<864, 256, GRAM_SMEM>>>();   // 4 <- profiled launch
    k_combineH<<<1024, 256>>>();         // 5
    k_combineE<<<1024, 256>>>(Y);        // 6
    k_scan<<<1, 1024>>>();               // 7
    k_s<<<384, 256>>>(X);                // 8
    k_b2<<<128, 256>>>(B2, w);           // 9

    const int KCH = 14;
    const double lo = 8.0, hi = 68.0;
    const double dm = 0.5 * (lo + hi), cr = 0.5 * (hi - lo);
    float alpha[KCH];
    for (int m = 0; m < KCH; ++m) {
        double node = dm + cr * cos(M_PI * (2.0 * m + 1.0) / (2.0 * KCH));
        alpha[m] = (float)(1.0 / node);
    }
    for (int p = 0; p < KCH; ++p) {
        int idx = (p & 1) ? (KCH - 1 - (p >> 1)) : (p >> 1);
        k_rich<<<1024, 256>>>(alpha[idx], p & 1);
    }

    k_final<<<1536, 256>>>(C2, D21, D22, xi, w, out);
}

// round 15
// speedup vs baseline: 1.0913x; 1.0913x over previous
#include <cuda_runtime.h>
#include <cuda_bf16.h>
#include <cstdint>
#include <math.h>

#define EPSV 0.001f
#define MM (1024*1024)

// ---------------- device scratch ----------------
__device__ __align__(16) __nv_bfloat16 g_Thi[3u*1024u*3072u];  // [col][k]
__device__ __align__(16) __nv_bfloat16 g_Tlo[3u*1024u*3072u];
__device__ float g_Pp[12u*MM];  // split-K partials: [mat*4+ks], mat 0:X1 1:X3 2:X2
__device__ float g_E[MM];
__device__ float g_H22[MM];
__device__ float g_t1[3072];
__device__ float g_s[3072];
__device__ float g_pre[1024];
__device__ float g_eps[1024];
__device__ float g_b[1024];
__device__ float g_xA[1024];
__device__ float g_xB[1024];

// ---------------- helpers ----------------
__device__ __forceinline__ float warpSum(float v) {
#pragma unroll
    for (int o = 16; o; o >>= 1) v += __shfl_down_sync(0xffffffffu, v, o);
    return v;
}
__device__ __forceinline__ float blockSum(float v) {
    __shared__ float sh[32];
    int lane = threadIdx.x & 31, wid = threadIdx.x >> 5;
    v = warpSum(v);
    if (lane == 0) sh[wid] = v;
    __syncthreads();
    if (wid == 0) {
        v = (lane < (int)(blockDim.x >> 5)) ? sh[lane] : 0.f;
        v = warpSum(v);
    }
    return v;
}
__device__ __forceinline__ float2 bf2f(uint32_t u) {
    __nv_bfloat162 h = *(__nv_bfloat162*)&u;
    return __bfloat1622float2(h);
}
__device__ __forceinline__ uint32_t smem_u32(const void* p) {
    uint32_t a;
    asm("{ .reg .u64 t; cvta.to.shared.u64 t, %1; cvt.u32.u64 %0, t; }" : "=r"(a) : "l"(p));
    return a;
}
#define CPA16(d, s) asm volatile("cp.async.ca.shared.global [%0], [%1], 16;" :: "r"(d), "l"(s))
#define CP_COMMIT() asm volatile("cp.async.commit_group;")
#define CP_WAIT0()  asm volatile("cp.async.wait_group 0;")
#define CP_WAIT1()  asm volatile("cp.async.wait_group 1;")
#define LDSM4(r0, r1, r2, r3, a) \
    asm volatile("ldmatrix.sync.aligned.m8n8.x4.shared.b16 {%0,%1,%2,%3}, [%4];" \
        : "=r"(r0), "=r"(r1), "=r"(r2), "=r"(r3) : "r"(a))
#define MMA_BF16(d, a, b) \
    asm volatile("mma.sync.aligned.m16n8k16.row.col.f32.bf16.bf16.f32 " \
        "{%0,%1,%2,%3},{%4,%5,%6,%7},{%8,%9},{%0,%1,%2,%3};" \
        : "+f"((d)[0]), "+f"((d)[1]), "+f"((d)[2]), "+f"((d)[3]) \
        : "r"((a)[0]), "r"((a)[1]), "r"((a)[2]), "r"((a)[3]), "r"((b)[0]), "r"((b)[1]))

// smem tile: 128 rows x 32 bf16 (64B/row), chunk swizzle c ^= (row>>1)&3
__device__ __forceinline__ uint32_t tileOff(int row, int c) {
    return (uint32_t)(row * 64 + ((c ^ ((row >> 1) & 3)) << 4));
}

// ---------------- t1 = X1 @ xi ----------------
__global__ void k_t1(const float* __restrict__ X, const float* __restrict__ xi) {
    int w = threadIdx.x >> 5, lane = threadIdx.x & 31;
    int r = blockIdx.x * 8 + w;
    const float4* row = (const float4*)(X + (size_t)r * 3072);
    const float4* xv4 = (const float4*)xi;
    float s = 0.f;
#pragma unroll
    for (int it = 0; it < 8; ++it) {
        float4 a = row[lane + it * 32];
        float4 b = xv4[lane + it * 32];
        s += a.x * b.x + a.y * b.y + a.z * b.z + a.w * b.w;
    }
    s = warpSum(s);
    if (lane == 0) g_t1[r] = s;
}

// ---------------- split & transpose: X -> bf16 hi/lo, [col][k], 64x64 tiles ----------------
__global__ __launch_bounds__(256) void k_split(const float* __restrict__ X) {
    __shared__ float tile[64][65];
    int bx = blockIdx.x % 48, by = blockIdx.x / 48;
    int c0 = bx * 64, r0 = by * 64;
    int tid = threadIdx.x;
#pragma unroll
    for (int it = 0; it < 16; ++it) {
        int elem = it * 256 + tid;
        int row = elem >> 6, col = elem & 63;
        tile[row][col] = X[(size_t)(r0 + row) * 3072 + c0 + col];
    }
    __syncthreads();
#pragma unroll
    for (int it = 0; it < 8; ++it) {
        int elem = it * 256 + tid;
        int col = elem >> 5, rp = elem & 31;
        float v0 = tile[2 * rp][col];
        float v1 = tile[2 * rp + 1][col];
        __nv_bfloat16 h0 = __float2bfloat16(v0);
        __nv_bfloat16 h1 = __float2bfloat16(v1);
        __nv_bfloat162 hi2; hi2.x = h0; hi2.y = h1;
        __nv_bfloat162 lo2;
        lo2.x = __float2bfloat16(v0 - __bfloat162float(h0));
        lo2.y = __float2bfloat16(v1 - __bfloat162float(h1));
        size_t o = ((size_t)(c0 + col) * 3072u + r0 + 2 * rp) >> 1;
        ((__nv_bfloat162*)g_Thi)[o] = hi2;
        ((__nv_bfloat162*)g_Tlo)[o] = lo2;
    }
}

// ---------------- pre = -X2^T t1 + D12 @ w ----------------
__global__ void k_pre2(const float* __restrict__ D12, const float* __restrict__ w) {
    int wid = threadIdx.x >> 5, lane = threadIdx.x & 31;
    int i = blockIdx.x * 8 + wid;
    const uint4* hi = (const uint4*)(g_Thi + (size_t)(1024 + i) * 3072);
    const uint4* lo = (const uint4*)(g_Tlo + (size_t)(1024 + i) * 3072);
    const float4* t1 = (const float4*)g_t1;
    float s = 0.f;
#pragma unroll
    for (int it = 0; it < 12; ++it) {
        int u = lane + it * 32;
        uint4 hv = hi[u];
        uint4 lv = lo[u];
        float4 ta = t1[2 * u], tb = t1[2 * u + 1];
        float2 h0 = bf2f(hv.x), l0 = bf2f(lv.x);
        float2 h1 = bf2f(hv.y), l1 = bf2f(lv.y);
        float2 h2 = bf2f(hv.z), l2 = bf2f(lv.z);
        float2 h3 = bf2f(hv.w), l3 = bf2f(lv.w);
        s += (h0.x + l0.x) * ta.x + (h0.y + l0.y) * ta.y + (h1.x + l1.x) * ta.z + (h1.y + l1.y) * ta.w;
        s += (h2.x + l2.x) * tb.x + (h2.y + l2.y) * tb.y + (h3.x + l3.x) * tb.z + (h3.y + l3.y) * tb.w;
    }
    const float4* dd = (const float4*)(D12 + (size_t)i * 512);
    const float4* wv = (const float4*)w;
    float s2 = 0.f;
#pragma unroll
    for (int it = 0; it < 4; ++it) {
        float4 a = dd[lane + it * 32];
        float4 b = wv[lane + it * 32];
        s2 += a.x * b.x + a.y * b.y + a.z * b.z + a.w * b.w;
    }
    float v = warpSum(s2 - s);
    if (lane == 0) g_pre[i] = v;
}

// ---------------- Gram GEMM via mma.sync, split-K 4 (432 CTAs), occ 2, 3-pass MMA order ----------------
#define GRAM_SMEM 66560
__global__ __launch_bounds__(256, 2) void k_gram() {
    extern __shared__ char smem[];
    uint32_t sb = smem_u32(smem);
    int tid = threadIdx.x;
    int lane = tid & 31, warp = tid >> 5;
    int warpM = warp & 1, warpN = warp >> 1;

    int job = blockIdx.x;          // 0..431
    int ks = job & 3;              // K chunk: ks*768
    int t = job >> 2;              // 0..107
    int mat = t / 36;
    int rem = t % 36, ti = 0, span = 8;
    while (rem >= span) { rem -= span; span--; ti++; }
    int tj = ti + rem;
    const int blkmap[3] = {0, 2, 1};
    size_t blkOff = (size_t)blkmap[mat] * (1024u * 3072u);
    float* outP = g_Pp + (size_t)(mat * 4 + ks) * MM;
    int i0 = ti * 128, j0 = tj * 128;
    int kOff = ks * 768;

    const __nv_bfloat16* srcs[4];
    srcs[0] = g_Thi + blkOff + (size_t)i0 * 3072 + kOff;
    srcs[1] = g_Tlo + blkOff + (size_t)i0 * 3072 + kOff;
    srcs[2] = g_Thi + blkOff + (size_t)j0 * 3072 + kOff;
    srcs[3] = g_Tlo + blkOff + (size_t)j0 * 3072 + kOff;

    float acc[4][4][4];
#pragma unroll
    for (int a = 0; a < 4; ++a)
#pragma unroll
        for (int b = 0; b < 4; ++b)
#pragma unroll
            for (int c = 0; c < 4; ++c) acc[a][b][c] = 0.f;

    int lrow = tid & 127;
    int lc0 = tid >> 7;
    const int NST = 24;  // 768 / 32

    {
        uint32_t sbase = sb;
#pragma unroll
        for (int pc = 0; pc < 4; ++pc) {
            const __nv_bfloat16* src = srcs[pc] + (size_t)lrow * 3072;
#pragma unroll
            for (int it = 0; it < 2; ++it) {
                int c = lc0 + it * 2;
                CPA16(sbase + pc * 8192u + tileOff(lrow, c), src + c * 8);
            }
        }
        CP_COMMIT();
    }

    for (int kt = 0; kt < NST; ++kt) {
        int s = kt & 1;
        if (kt + 1 < NST) {
            uint32_t sbase = sb + (uint32_t)((kt + 1) & 1) * 32768u;
            int kIdx = (kt + 1) * 32;
#pragma unroll
            for (int pc = 0; pc < 4; ++pc) {
                const __nv_bfloat16* src = srcs[pc] + (size_t)lrow * 3072 + kIdx;
#pragma unroll
                for (int it = 0; it < 2; ++it) {
                    int c = lc0 + it * 2;
                    CPA16(sbase + pc * 8192u + tileOff(lrow, c), src + c * 8);
                }
            }
            CP_COMMIT();
            CP_WAIT1();
        } else {
            CP_WAIT0();
        }
        __syncthreads();

        uint32_t SA_hi = sb + (uint32_t)s * 32768u;
        uint32_t SA_lo = SA_hi + 8192u;
        uint32_t SB_hi = SA_hi + 16384u;
        uint32_t SB_lo = SA_hi + 24576u;

#pragma unroll
        for (int kb = 0; kb < 2; ++kb) {
            uint32_t ah[4][4], al[4][4], bh[4][2], bl[4][2];
            int rA = warpM * 64 + (lane & 15);
            int cA = kb * 2 + (lane >> 4);
#pragma unroll
            for (int mi = 0; mi < 4; ++mi) {
                uint32_t off = tileOff(rA + mi * 16, cA);
                LDSM4(ah[mi][0], ah[mi][1], ah[mi][2], ah[mi][3], SA_hi + off);
                LDSM4(al[mi][0], al[mi][1], al[mi][2], al[mi][3], SA_lo + off);
            }
            int grp = lane >> 3;
            int cB = kb * 2 + (grp & 1);
#pragma unroll
            for (int p = 0; p < 2; ++p) {
                int row = warpN * 32 + (p * 2 + (grp >> 1)) * 8 + (lane & 7);
                uint32_t off = tileOff(row, cB);
                uint32_t r0, r1, r2, r3;
                LDSM4(r0, r1, r2, r3, SB_hi + off);
                bh[p * 2][0] = r0; bh[p * 2][1] = r1;
                bh[p * 2 + 1][0] = r2; bh[p * 2 + 1][1] = r3;
                LDSM4(r0, r1, r2, r3, SB_lo + off);
                bl[p * 2][0] = r0; bl[p * 2][1] = r1;
                bl[p * 2 + 1][0] = r2; bl[p * 2 + 1][1] = r3;
            }
            // 3 product passes: same-acc reuse distance = 16 issues (hides HMMA latency)
#pragma unroll
            for (int mi = 0; mi < 4; ++mi)
#pragma unroll
                for (int ni = 0; ni < 4; ++ni)
                    MMA_BF16(acc[mi][ni], ah[mi], bh[ni]);
#pragma unroll
            for (int mi = 0; mi < 4; ++mi)
#pragma unroll
                for (int ni = 0; ni < 4; ++ni)
                    MMA_BF16(acc[mi][ni], ah[mi], bl[ni]);
#pragma unroll
            for (int mi = 0; mi < 4; ++mi)
#pragma unroll
                for (int ni = 0; ni < 4; ++ni)
                    MMA_BF16(acc[mi][ni], al[mi], bh[ni]);
        }
        __syncthreads();
    }

    // epilogue: stage through smem (129 pitch), write both mirrored halves coalesced
    float (*Ts)[129] = (float(*)[129])smem;
    int g = lane >> 2, tg = lane & 3;
#pragma unroll
    for (int mi = 0; mi < 4; ++mi) {
        int r0 = warpM * 64 + mi * 16 + g;
#pragma unroll
        for (int ni = 0; ni < 4; ++ni) {
            int col = warpN * 32 + ni * 8 + tg * 2;
            Ts[r0][col] = acc[mi][ni][0];
            Ts[r0][col + 1] = acc[mi][ni][1];
            Ts[r0 + 8][col] = acc[mi][ni][2];
            Ts[r0 + 8][col + 1] = acc[mi][ni][3];
        }
    }
    __syncthreads();
    {
        int row = tid >> 1, ch = (tid & 1) * 64;
        float* o = outP + (size_t)(i0 + row) * 1024 + j0 + ch;
#pragma unroll
        for (int q = 0; q < 16; ++q) {
            float4 v = make_float4(Ts[row][ch + 4 * q], Ts[row][ch + 4 * q + 1],
                                   Ts[row][ch + 4 * q + 2], Ts[row][ch + 4 * q + 3]);
            ((float4*)o)[q] = v;
        }
        if (ti != tj) {
            float* o2 = outP + (size_t)(j0 + row) * 1024 + i0 + ch;
#pragma unroll
            for (int q = 0; q < 16; ++q) {
                float4 v = make_float4(Ts[ch + 4 * q][row], Ts[ch + 4 * q + 1][row],
                                       Ts[ch + 4 * q + 2][row], Ts[ch + 4 * q + 3][row]);
                ((float4*)o2)[q] = v;
            }
        }
    }
}

// ---------------- combineH: H22 = sum of 4 partials ----------------
__global__ void k_combineH() {
    int i = blockIdx.x * 256 + threadIdx.x;  // grid 1024, float4
    float4 r = make_float4(0.f, 0.f, 0.f, 0.f);
#pragma unroll
    for (int p = 8; p < 12; ++p) {
        float4 a = ((const float4*)(g_Pp + (size_t)p * MM))[i];
        r.x += a.x; r.y += a.y; r.z += a.z; r.w += a.w;
    }
    ((float4*)g_H22)[i] = r;
}

// ---------------- combineE: E = 0.5(ΣPE + Y - Y^T) + epsI ----------------
__global__ void k_combineE(const float* __restrict__ Y) {
    __shared__ float Yt[32][33];
    int bj = blockIdx.x & 31, bi = blockIdx.x >> 5;
    int tx = threadIdx.x & 31, ty = threadIdx.x >> 5;
#pragma unroll
    for (int it = 0; it < 4; ++it) {
        int jr = bj * 32 + ty + it * 8;
        Yt[ty + it * 8][tx] = Y[(size_t)jr * 1024 + bi * 32 + tx];
    }
    __syncthreads();
#pragma unroll
    for (int it = 0; it < 4; ++it) {
        int i = bi * 32 + ty + it * 8;
        int j = bj * 32 + tx;
        size_t idx = (size_t)i * 1024 + j;
        float s = 0.f;
#pragma unroll
        for (int p = 0; p < 8; ++p) s += g_Pp[(size_t)p * MM + idx];
        float e = 0.5f * (s + Y[idx] - Yt[tx][ty + it * 8]);
        if (i == j) e += EPSV;
        g_E[idx] = e;
    }
}

// ---------------- blocked tanh forward substitution (chunk=32) ----------------
__global__ __launch_bounds__(1024) void k_scan() {
    int j = threadIdx.x, wid = j >> 5, lane = j & 31;
    __shared__ float s_eps[1024];
    float accJ = 0.f;
    float pre_j = g_pre[j];
    float li = 1.0f / (g_H22[(size_t)j * 1024 + j] + EPSV);
    for (int c = 0; c < 32; ++c) {
        int base = c * 32;
        if (wid == c) {
            float colreg[32];
#pragma unroll
            for (int k = 0; k < 32; ++k)
                colreg[k] = g_H22[(size_t)(base + k) * 1024 + base + lane];
            float within = 0.f, myeps = 0.f;
            float v_base = pre_j + accJ;
#pragma unroll
            for (int k = 0; k < 32; ++k) {
                if (lane == k) myeps = tanhf((v_base + within) * li);
                float e = __shfl_sync(0xffffffffu, myeps, k);
                if (lane > k) within = fmaf(-colreg[k], e, within);
            }
            s_eps[base + lane] = myeps;
        }
        __syncthreads();
        if (j >= base + 32) {
#pragma unroll
            for (int k = 0; k < 32; ++k)
                accJ = fmaf(-g_H22[(size_t)(base + k) * 1024 + j], s_eps[base + k], accJ);
        }
    }
    g_eps[j] = s_eps[j];
}

// ---------------- s = t1 + X2 @ eps ----------------
__global__ void k_s(const float* __restrict__ X) {
    int w = threadIdx.x >> 5, lane = threadIdx.x & 31;
    int r = blockIdx.x * 8 + w;
    const float4* row = (const float4*)(X + (size_t)r * 3072 + 1024);
    const float4* ev4 = (const float4*)g_eps;
    float s = 0.f;
#pragma unroll
    for (int it = 0; it < 8; ++it) {
        float4 a = row[lane + it * 32];
        float4 b = ev4[lane + it * 32];
        s += a.x * b.x + a.y * b.y + a.z * b.z + a.w * b.w;
    }
    s = warpSum(s);
    if (lane == 0) g_s[r] = g_t1[r] + s;
}

// ---------------- b = X3^T s + B2 @ w ----------------
__global__ void k_b2(const float* __restrict__ B2, const float* __restrict__ w) {
    int wid = threadIdx.x >> 5, lane = threadIdx.x & 31;
    int i = blockIdx.x * 8 + wid;
    const uint4* hi = (const uint4*)(g_Thi + (size_t)(2048 + i) * 3072);
    const uint4* lo = (const uint4*)(g_Tlo + (size_t)(2048 + i) * 3072);
    const float4* sv = (const float4*)g_s;
    float s = 0.f;
#pragma unroll
    for (int it = 0; it < 12; ++it) {
        int u = lane + it * 32;
        uint4 hv = hi[u];
        uint4 lv = lo[u];
        float4 ta = sv[2 * u], tb = sv[2 * u + 1];
        float2 h0 = bf2f(hv.x), l0 = bf2f(lv.x);
        float2 h1 = bf2f(hv.y), l1 = bf2f(lv.y);
        float2 h2 = bf2f(hv.z), l2 = bf2f(lv.z);
        float2 h3 = bf2f(hv.w), l3 = bf2f(lv.w);
        s += (h0.x + l0.x) * ta.x + (h0.y + l0.y) * ta.y + (h1.x + l1.x) * ta.z + (h1.y + l1.y) * ta.w;
        s += (h2.x + l2.x) * tb.x + (h2.y + l2.y) * tb.y + (h3.x + l3.x) * tb.z + (h3.y + l3.y) * tb.w;
    }
    const float4* bb = (const float4*)(B2 + (size_t)i * 512);
    const float4* wv = (const float4*)w;
    float s2 = 0.f;
#pragma unroll
    for (int it = 0; it < 4; ++it) {
        float4 a = bb[lane + it * 32];
        float4 b = wv[lane + it * 32];
        s2 += a.x * b.x + a.y * b.y + a.z * b.z + a.w * b.w;
    }
    float v = warpSum(s + s2);
    if (lane == 0) { g_b[i] = v; g_xA[i] = 0.f; }
}

// ---------------- Richardson step ----------------
__global__ void k_rich(float alpha, int flip) {
    const float* xs = flip ? g_xB : g_xA;
    float* xd = flip ? g_xA : g_xB;
    int i = blockIdx.x;
    int t = threadIdx.x;
    const float4* Er = (const float4*)(g_E + (size_t)i * 1024);
    const float4* xv = (const float4*)xs;
    float4 e = Er[t];
    float4 x = xv[t];
    float s = e.x * x.x + e.y * x.y + e.z * x.z + e.w * x.w;
    s = blockSum(s);
    if (t == 0) xd[i] = xs[i] + alpha * (g_b[i] - s);
}

// ---------------- output assembly ----------------
__global__ void k_final(const float* __restrict__ C2, const float* __restrict__ D21,
                        const float* __restrict__ D22, const float* __restrict__ xi,
                        const float* __restrict__ w, float* __restrict__ out) {
    int i = blockIdx.x;
    if (i >= 512) {
        if (threadIdx.x == 0) out[i] = g_xA[i - 512];
        return;
    }
    int t = threadIdx.x;
    float s = 0.f;
    for (int k = t; k < 1024; k += 256)
        s += C2[i * 1024 + k] * xi[k] + D21[i * 1024 + k] * g_eps[k];
    for (int k = t; k < 512; k += 256) s += D22[i * 512 + k] * w[k];
    float v = blockSum(s);
    if (t == 0) out[i] = v;
}

// ---------------- host ----------------
extern "C" void kernel_launch(void* const* d_in, const int* in_sizes, int n_in,
                              void* d_out, int out_size) {
    const float* w   = (const float*)d_in[1];
    const float* xi  = (const float*)d_in[2];
    const float* X   = (const float*)d_in[3];
    const float* Y   = (const float*)d_in[4];
    const float* B2  = (const float*)d_in[5];
    const float* C2  = (const float*)d_in[6];
    const float* D21 = (const float*)d_in[7];
    const float* D22 = (const float*)d_in[8];
    const float* D12 = (const float*)d_in[9];
    float* out = (float*)d_out;

    cudaFuncSetAttribute(k_gram, cudaFuncAttributeMaxDynamicSharedMemorySize, GRAM_SMEM);

    k_t1<<<384, 256>>>(X, xi);           // 1
    k_split<<<2304, 256>>>(X);           // 2
    k_pre2<<<128, 256>>>(D12, w);        // 3
    k_gram<<<432, 256, GRAM_SMEM>>>();   // 4 <- profiled launch
    k_combineH<<<1024, 256>>>();         // 5
    k_combineE<<<1024, 256>>>(Y);        // 6
    k_scan<<<1, 1024>>>();               // 7
    k_s<<<384, 256>>>(X);                // 8
    k_b2<<<128, 256>>>(B2, w);           // 9

    const int KCH = 14;
    const double lo = 8.0, hi = 68.0;
    const double dm = 0.5 * (lo + hi), cr = 0.5 * (hi - lo);
    float alpha[KCH];
    for (int m = 0; m < KCH; ++m) {
        double node = dm + cr * cos(M_PI * (2.0 * m + 1.0) / (2.0 * KCH));
        alpha[m] = (float)(1.0 / node);
    }
    for (int p = 0; p < KCH; ++p) {
        int idx = (p & 1) ? (KCH - 1 - (p >> 1)) : (p >> 1);
        k_rich<<<1024, 256>>>(alpha[idx], p & 1);
    }

    k_final<<<1536, 256>>>(C2, D21, D22, xi, w, out);
}